// round 5
// baseline (speedup 1.0000x reference)
#include <cuda_runtime.h>

#define LSEQ 256
#define CIN  8
#define COUT 8
#define HID  32
#define XPAD 12     // padded row stride (floats) for conflict-free LDS.128
#define NBLK 128

// Scratch: K[o][d][c]
__device__ __align__(16) float g_K[COUT * LSEQ * CIN];
// Grid barrier state (self-resetting for graph replay)
__device__ volatile unsigned g_bar  = 0;
__device__ unsigned          g_done = 0;

// ---------------------------------------------------------------------------
// Fused kernel: phase 1 = SIREN kernel-net at 16384 (o,d,c) points
// (split-k x2: adjacent lanes share a point), software grid barrier,
// phase 2 = causal conv from shared memory.
// Grid MUST be 128 blocks (all co-resident, 1 wave) for the spin barrier.
// ---------------------------------------------------------------------------
__global__ __launch_bounds__(256, 1) void ckconv_fused(
    const float* __restrict__ x,
    const float* __restrict__ v1, const float* __restrict__ g1,
    const float* __restrict__ b1,
    const float* __restrict__ v2, const float* __restrict__ g2,
    const float* __restrict__ b2,
    const float* __restrict__ w3, const float* __restrict__ b3,
    float* __restrict__ out)
{
    __shared__ float  sW1[HID][3];
    __shared__ float  sb1[HID];
    __shared__ float4 sW2[HID][HID / 4];
    __shared__ float  sb2[HID];
    __shared__ float  sw3[HID];
    __shared__ float  sinv2[HID];
    __shared__ float  sk[LSEQ * XPAD];   // conv: K[o] staged
    __shared__ float  sx[LSEQ * XPAD];   // conv: x staged

    int tid = threadIdx.x;

    // ---------------- phase 0: stage x (independent of g_K) ---------------
    const float4* x4 = (const float4*)x;
    {
        int r = tid >> 1, hh = (tid & 1) << 2;
        *(float4*)&sx[r * XPAD + hh] = x4[tid];
        *(float4*)&sx[(r + 128) * XPAD + hh] = x4[tid + 256];
    }

    // ---------------- phase 1: SIREN kernel-net ----------------------------
    // W2 row norms cooperatively: thread t owns float4 #t of v2
    float4 w4 = ((const float4*)v2)[tid];
    float ss = w4.x * w4.x + w4.y * w4.y + w4.z * w4.z + w4.w * w4.w;
    ss += __shfl_xor_sync(0xFFFFFFFFu, ss, 1);
    ss += __shfl_xor_sync(0xFFFFFFFFu, ss, 2);
    ss += __shfl_xor_sync(0xFFFFFFFFu, ss, 4);
    int row = tid >> 3;
    if ((tid & 7) == 0)
        sinv2[row] = g2[row] * rsqrtf(ss);

    if (tid < HID) {
        float a = v1[tid * 3 + 0];
        float b = v1[tid * 3 + 1];
        float c = v1[tid * 3 + 2];
        float inv1 = g1[tid] * rsqrtf(a * a + b * b + c * c);
        sW1[tid][0] = a * inv1;
        sW1[tid][1] = b * inv1;
        sW1[tid][2] = c * inv1;
        sb1[tid] = b1[tid];
        sb2[tid] = b2[tid];
        sw3[tid] = w3[tid];
    }
    __syncthreads();

    float inv = sinv2[row];
    float4 nw;
    nw.x = w4.x * inv; nw.y = w4.y * inv; nw.z = w4.z * inv; nw.w = w4.w * inv;
    ((float4*)sW2)[tid] = nw;
    __syncthreads();

    // point eval: gt -> pid; adjacent lanes split the hidden dimension
    int gt   = blockIdx.x * 256 + tid;
    int pid  = gt >> 1;
    int half = tid & 1;
    int c = pid & 7;
    int d = (pid >> 3) & 255;
    int o = pid >> 11;

    float dt = -(float)d * (1.0f / 256.0f);
    float fc = (float)c;
    float fo = (float)o;

    int hbase = half << 4;
    float h1[HID];
    #pragma unroll
    for (int m = 0; m < 16; m++) {
        int h = hbase + m;
        float z = fmaf(dt, sW1[h][0], fmaf(fc, sW1[h][1], fmaf(fo, sW1[h][2], sb1[h])));
        h1[m] = __sinf(z);              // OMEGA = 1
    }
    #pragma unroll
    for (int m = 0; m < 16; m++)
        h1[16 + m] = __shfl_xor_sync(0xFFFFFFFFu, h1[m], 1);

    int my4 = half << 2;
    int ot4 = my4 ^ 4;

    float acc = 0.f;
    #pragma unroll
    for (int m = 0; m < 16; m++) {
        int k = hbase + m;
        const float4* rw = &sW2[k][0];
        float z = sb2[k];
        #pragma unroll
        for (int q = 0; q < 4; q++) {
            float4 w = rw[my4 + q];
            z = fmaf(h1[4*q+0], w.x, z);
            z = fmaf(h1[4*q+1], w.y, z);
            z = fmaf(h1[4*q+2], w.z, z);
            z = fmaf(h1[4*q+3], w.w, z);
        }
        #pragma unroll
        for (int q = 0; q < 4; q++) {
            float4 w = rw[ot4 + q];
            z = fmaf(h1[16+4*q+0], w.x, z);
            z = fmaf(h1[16+4*q+1], w.y, z);
            z = fmaf(h1[16+4*q+2], w.z, z);
            z = fmaf(h1[16+4*q+3], w.w, z);
        }
        acc = fmaf(__sinf(z), sw3[k], acc);
    }
    acc += __shfl_xor_sync(0xFFFFFFFFu, acc, 1);
    if (half == 0)
        g_K[pid] = acc + b3[0];

    // ---------------- grid barrier -----------------------------------------
    __threadfence();          // publish g_K
    __syncthreads();          // whole block arrived
    if (tid == 0) {
        atomicAdd((unsigned*)&g_bar, 1u);
        while (g_bar < NBLK) { }
    }
    __syncthreads();          // block released; orders spin before sk loads

    // ---------------- phase 2: causal conv ---------------------------------
    int oc   = blockIdx.x >> 4;          // out channel for this block
    int base = (blockIdx.x & 15) << 4;   // i-tile base (16 positions)

    const float4* k4 = (const float4*)(g_K + oc * (LSEQ * CIN));
    {
        int r = tid >> 1, hh = (tid & 1) << 2;
        float4 a = __ldcg(k4 + tid);            // L2-coherent (written by peers)
        float4 b = __ldcg(k4 + tid + 256);
        *(float4*)&sk[r * XPAD + hh] = a;
        *(float4*)&sk[(r + 128) * XPAD + hh] = b;
    }
    __syncthreads();

    int w = tid >> 5, l = tid & 31;
    int i0 = base + 2 * w;
    int i1 = i0 + 1;

    float acc0 = 0.f, acc1 = 0.f;
    #pragma unroll
    for (int it = 0; it < 8; it++) {
        if ((it << 5) > i1) break;       // warp-uniform early exit
        int dd = l + (it << 5);
        float4 ka = *(const float4*)&sk[dd * XPAD];
        float4 kb = *(const float4*)&sk[dd * XPAD + 4];

        int j1 = i1 - dd;
        bool v0 = dd <= i0, v1 = dd <= i1;
        int jc0 = v0 ? (j1 - 1) : 0;
        int jc1 = v1 ? j1 : 0;
        float m0 = v0 ? 1.f : 0.f;
        float m1 = v1 ? 1.f : 0.f;

        float4 a0 = *(const float4*)&sx[jc0 * XPAD];
        float4 b0 = *(const float4*)&sx[jc0 * XPAD + 4];
        float4 a1 = *(const float4*)&sx[jc1 * XPAD];
        float4 b1 = *(const float4*)&sx[jc1 * XPAD + 4];

        float t0 = ka.x * a0.x;
        t0 = fmaf(ka.y, a0.y, t0);
        t0 = fmaf(ka.z, a0.z, t0);
        t0 = fmaf(ka.w, a0.w, t0);
        t0 = fmaf(kb.x, b0.x, t0);
        t0 = fmaf(kb.y, b0.y, t0);
        t0 = fmaf(kb.z, b0.z, t0);
        t0 = fmaf(kb.w, b0.w, t0);
        acc0 = fmaf(m0, t0, acc0);

        float t1 = ka.x * a1.x;
        t1 = fmaf(ka.y, a1.y, t1);
        t1 = fmaf(ka.z, a1.z, t1);
        t1 = fmaf(ka.w, a1.w, t1);
        t1 = fmaf(kb.x, b1.x, t1);
        t1 = fmaf(kb.y, b1.y, t1);
        t1 = fmaf(kb.z, b1.z, t1);
        t1 = fmaf(kb.w, b1.w, t1);
        acc1 = fmaf(m1, t1, acc1);
    }

    #pragma unroll
    for (int s = 16; s > 0; s >>= 1) {
        acc0 += __shfl_xor_sync(0xFFFFFFFFu, acc0, s);
        acc1 += __shfl_xor_sync(0xFFFFFFFFu, acc1, s);
    }

    if (l == 0) {
        out[i0 * COUT + oc] = acc0;
        out[i1 * COUT + oc] = acc1;
    }

    // ---------------- barrier reset for next graph replay ------------------
    __syncthreads();
    if (tid == 0) {
        if (atomicAdd(&g_done, 1u) == NBLK - 1u) {
            g_done = 0u;
            *(unsigned*)&g_bar = 0u;
        }
    }
}

// ---------------------------------------------------------------------------
// Launch. Input order: x, t, v1, g1, b1, v2, g2, b2, w3, b3.
// t is the uniform grid arange(L)/L; folded analytically into dt = -d/L.
// ---------------------------------------------------------------------------
extern "C" void kernel_launch(void* const* d_in, const int* in_sizes, int n_in,
                              void* d_out, int out_size)
{
    const float* x  = (const float*)d_in[0];
    const float* v1 = (const float*)d_in[2];
    const float* g1 = (const float*)d_in[3];
    const float* b1 = (const float*)d_in[4];
    const float* v2 = (const float*)d_in[5];
    const float* g2 = (const float*)d_in[6];
    const float* b2 = (const float*)d_in[7];
    const float* w3 = (const float*)d_in[8];
    const float* b3 = (const float*)d_in[9];
    float* out = (float*)d_out;

    ckconv_fused<<<NBLK, 256>>>(x, v1, g1, b1, v2, g2, b2, w3, b3, out);
}

// round 7
// speedup vs baseline: 1.0118x; 1.0118x over previous
#include <cuda_runtime.h>

#define LSEQ 256
#define CIN  8
#define COUT 8
#define HID  32
#define XPAD 12     // padded row stride (floats) for conflict-free LDS.128
#define NBLK 128
#define NTHR 512
#define GRP  16     // blocks per o-group

// Scratch: K[o][d][c]
__device__ __align__(16) float g_K[COUT * LSEQ * CIN];
// Per-group barrier state (self-resetting for graph replay)
__device__ volatile unsigned g_bar[COUT] = {0};
__device__ unsigned          g_dep[COUT] = {0};

// ---------------------------------------------------------------------------
// Fused kernel, grid = 128 blocks x 512 threads (single wave on 148 SMs).
// Phase 1: SIREN kernel-net at 16384 (o,d,c) points, split-k x4
//          (4 adjacent lanes share a point; each computes 8 h1 values and
//           8 output neurons; h1 exchanged via 24 shfls).
// Group barrier: 8 independent groups of 16 blocks (group g == channel o).
// Phase 2: causal conv from shared memory, 16 warps = 16 output positions.
// ---------------------------------------------------------------------------
__global__ __launch_bounds__(NTHR, 1) void ckconv_fused(
    const float* __restrict__ x,
    const float* __restrict__ v1, const float* __restrict__ g1,
    const float* __restrict__ b1,
    const float* __restrict__ v2, const float* __restrict__ g2,
    const float* __restrict__ b2,
    const float* __restrict__ w3, const float* __restrict__ b3,
    float* __restrict__ out)
{
    __shared__ float  sW1[HID][3];
    __shared__ float  sb1[HID];
    __shared__ float4 sW2[HID][HID / 4];
    __shared__ float  sb2[HID];
    __shared__ float  sw3[HID];
    __shared__ float  sb3;
    __shared__ __align__(16) float sk[LSEQ * XPAD];   // 16B-aligned: float4 access
    __shared__ __align__(16) float sx[LSEQ * XPAD];

    int tid = threadIdx.x;

    // ---------------- phase 0: stage x (independent of g_K) ----------------
    const float4* x4 = (const float4*)x;
    {
        int r = tid >> 1, hh = (tid & 1) << 2;
        *(float4*)&sx[r * XPAD + hh] = x4[tid];   // 512 float4 = all of x
    }

    // ---------------- weight prep ------------------------------------------
    if (tid < 256) {
        float4 w4 = ((const float4*)v2)[tid];
        float ss = w4.x * w4.x + w4.y * w4.y + w4.z * w4.z + w4.w * w4.w;
        ss += __shfl_xor_sync(0xFFFFFFFFu, ss, 1);
        ss += __shfl_xor_sync(0xFFFFFFFFu, ss, 2);
        ss += __shfl_xor_sync(0xFFFFFFFFu, ss, 4);
        int row = tid >> 3;
        float inv = g2[row] * rsqrtf(ss);
        float4 nw;
        nw.x = w4.x * inv; nw.y = w4.y * inv; nw.z = w4.z * inv; nw.w = w4.w * inv;
        ((float4*)sW2)[tid] = nw;
    }
    if (tid < HID) {
        float a = v1[tid * 3 + 0];
        float b = v1[tid * 3 + 1];
        float c = v1[tid * 3 + 2];
        float inv1 = g1[tid] * rsqrtf(a * a + b * b + c * c);
        sW1[tid][0] = a * inv1;
        sW1[tid][1] = b * inv1;
        sW1[tid][2] = c * inv1;
        sb1[tid] = b1[tid];
        sb2[tid] = b2[tid];
        sw3[tid] = w3[tid];
        if (tid == 0) sb3 = b3[0];
    }
    __syncthreads();

    // ---------------- phase 1: point eval (split-k x4) ----------------------
    // gt in [0, 65536); 4 consecutive lanes share pid = gt >> 2.
    int gt  = blockIdx.x * NTHR + tid;
    int pid = gt >> 2;
    int q   = tid & 3;                 // quarter within the point
    int c = pid & 7;
    int d = (pid >> 3) & 255;
    int o = pid >> 11;

    float dt = -(float)d * (1.0f / 256.0f);
    float fc = (float)c;
    float fo = (float)o;

    // my 8 h1 values: h = 8q + m
    float own[8];
    #pragma unroll
    for (int m = 0; m < 8; m++) {
        int h = (q << 3) + m;
        float z = fmaf(dt, sW1[h][0], fmaf(fc, sW1[h][1], fmaf(fo, sW1[h][2], sb1[h])));
        own[m] = __sinf(z);            // OMEGA = 1
    }
    // exchange: a8 = quad q^1, b8 = quad q^2, c8 = quad q^3
    float a8[8], b8[8], c8[8];
    #pragma unroll
    for (int m = 0; m < 8; m++) a8[m] = __shfl_xor_sync(0xFFFFFFFFu, own[m], 1);
    #pragma unroll
    for (int m = 0; m < 8; m++) b8[m] = __shfl_xor_sync(0xFFFFFFFFu, own[m], 2);
    #pragma unroll
    for (int m = 0; m < 8; m++) c8[m] = __shfl_xor_sync(0xFFFFFFFFu, a8[m], 2);

    // quad bases in units of float4 within a W2 row
    int p0 = q << 1;                  // my quad:   h = 8q + m
    int p1 = (q ^ 1) << 1;
    int p2 = (q ^ 2) << 1;
    int p3 = (q ^ 3) << 1;

    float acc = 0.f;
    #pragma unroll
    for (int kk = 0; kk < 8; kk++) {
        int k = (q << 3) + kk;
        const float4* rw = &sW2[k][0];
        float z = sb2[k];
        float4 w;
        w = rw[p0 + 0];
        z = fmaf(own[0], w.x, z); z = fmaf(own[1], w.y, z);
        z = fmaf(own[2], w.z, z); z = fmaf(own[3], w.w, z);
        w = rw[p0 + 1];
        z = fmaf(own[4], w.x, z); z = fmaf(own[5], w.y, z);
        z = fmaf(own[6], w.z, z); z = fmaf(own[7], w.w, z);
        w = rw[p1 + 0];
        z = fmaf(a8[0], w.x, z); z = fmaf(a8[1], w.y, z);
        z = fmaf(a8[2], w.z, z); z = fmaf(a8[3], w.w, z);
        w = rw[p1 + 1];
        z = fmaf(a8[4], w.x, z); z = fmaf(a8[5], w.y, z);
        z = fmaf(a8[6], w.z, z); z = fmaf(a8[7], w.w, z);
        w = rw[p2 + 0];
        z = fmaf(b8[0], w.x, z); z = fmaf(b8[1], w.y, z);
        z = fmaf(b8[2], w.z, z); z = fmaf(b8[3], w.w, z);
        w = rw[p2 + 1];
        z = fmaf(b8[4], w.x, z); z = fmaf(b8[5], w.y, z);
        z = fmaf(b8[6], w.z, z); z = fmaf(b8[7], w.w, z);
        w = rw[p3 + 0];
        z = fmaf(c8[0], w.x, z); z = fmaf(c8[1], w.y, z);
        z = fmaf(c8[2], w.z, z); z = fmaf(c8[3], w.w, z);
        w = rw[p3 + 1];
        z = fmaf(c8[4], w.x, z); z = fmaf(c8[5], w.y, z);
        z = fmaf(c8[6], w.z, z); z = fmaf(c8[7], w.w, z);
        acc = fmaf(__sinf(z), sw3[k], acc);
    }
    acc += __shfl_xor_sync(0xFFFFFFFFu, acc, 1);
    acc += __shfl_xor_sync(0xFFFFFFFFu, acc, 2);
    if (q == 0)
        g_K[pid] = acc + sb3;

    // ---------------- group barrier (16 blocks sharing o) -------------------
    int grp = blockIdx.x >> 4;        // == the o this group produces & consumes
    __threadfence();                  // publish g_K
    __syncthreads();
    if (tid == 0) {
        atomicAdd((unsigned*)&g_bar[grp], 1u);
        while (g_bar[grp] < GRP) { }
    }
    __syncthreads();

    // ---------------- phase 2: causal conv ----------------------------------
    int oc   = grp;
    int base = (blockIdx.x & 15) << 4;   // 16 positions per block

    const float4* k4 = (const float4*)(g_K + oc * (LSEQ * CIN));
    {
        int r = tid >> 1, hh = (tid & 1) << 2;
        float4 kv = __ldcg(k4 + tid);     // L2-coherent (written by peer blocks)
        *(float4*)&sk[r * XPAD + hh] = kv;
    }
    __syncthreads();

    int w = tid >> 5, l = tid & 31;   // 16 warps -> 16 output positions
    int i = base + w;

    float acc2 = 0.f;
    #pragma unroll
    for (int it = 0; it < 8; it++) {
        if ((it << 5) > i) break;     // warp-uniform early exit
        int dd = l + (it << 5);
        float4 ka = *(const float4*)&sk[dd * XPAD];
        float4 kb = *(const float4*)&sk[dd * XPAD + 4];

        bool v = dd <= i;
        int jc = v ? (i - dd) : 0;
        float m = v ? 1.f : 0.f;

        float4 a0 = *(const float4*)&sx[jc * XPAD];
        float4 b0 = *(const float4*)&sx[jc * XPAD + 4];

        float t = ka.x * a0.x;
        t = fmaf(ka.y, a0.y, t);
        t = fmaf(ka.z, a0.z, t);
        t = fmaf(ka.w, a0.w, t);
        t = fmaf(kb.x, b0.x, t);
        t = fmaf(kb.y, b0.y, t);
        t = fmaf(kb.z, b0.z, t);
        t = fmaf(kb.w, b0.w, t);
        acc2 = fmaf(m, t, acc2);
    }

    #pragma unroll
    for (int s = 16; s > 0; s >>= 1)
        acc2 += __shfl_xor_sync(0xFFFFFFFFu, acc2, s);

    if (l == 0)
        out[i * COUT + oc] = acc2;

    // ---------------- barrier reset (depart counter, replay-safe) -----------
    __syncthreads();
    if (tid == 0) {
        if (atomicAdd(&g_dep[grp], 1u) == GRP - 1u) {
            // all 16 group blocks have exited the spin: safe to reset
            g_dep[grp] = 0u;
            *(unsigned*)&g_bar[grp] = 0u;
        }
    }
}

// ---------------------------------------------------------------------------
// Launch. Input order: x, t, v1, g1, b1, v2, g2, b2, w3, b3.
// t is the uniform grid arange(L)/L; folded analytically into dt = -d/L.
// ---------------------------------------------------------------------------
extern "C" void kernel_launch(void* const* d_in, const int* in_sizes, int n_in,
                              void* d_out, int out_size)
{
    const float* x  = (const float*)d_in[0];
    const float* v1 = (const float*)d_in[2];
    const float* g1 = (const float*)d_in[3];
    const float* b1 = (const float*)d_in[4];
    const float* v2 = (const float*)d_in[5];
    const float* g2 = (const float*)d_in[6];
    const float* b2 = (const float*)d_in[7];
    const float* w3 = (const float*)d_in[8];
    const float* b3 = (const float*)d_in[9];
    float* out = (float*)d_out;

    ckconv_fused<<<NBLK, NTHR>>>(x, v1, g1, b1, v2, g2, b2, w3, b3, out);
}